// round 11
// baseline (speedup 1.0000x reference)
#include <cuda_runtime.h>
#include <cuda_fp16.h>
#include <cstdint>

// ============================================================================
// EdgeCompute: out[e] = sigmoid(relu(|x[i0[e]] - x[i1[e]]| @ W1 + b1) @ W2 + b2)
// R10: TILE_E 16->32 (B-fragment traffic per edge halves: 16KB W1 amortized
// over 2x edges) combined with the fp16 pre-converted gather from R8.
// L1 wavefronts/edge: gather 4 + A-store 2 + A-read 2 + B-read 4 = 12 (was 16).
// Cost: acc regs double -> WPC 28->21 (occ ~33%). Persistent kernel,
// warp-independent tiles, pure fp16 single-term m16n8k16 (rel_err ~1e-4).
// Inline index-dtype detection (int32 vs JAX-demoted int64).
// ============================================================================

#define D_FEAT 128
#define HID 64
#define WPC 21
#define THREADS (WPC * 32)
#define TILE_E 32
#define MAX_NODES 16384

#define A_ROW_B   272                   // 128 fp16 + 16B pad -> conflict-free frags
#define A_WARP_B  (TILE_E * A_ROW_B)    // 8704
#define SM_A      0
#define SM_B      (WPC * A_WARP_B)      // 182784: 8 ks x 4 ns-pairs x 32 lanes x uint4
#define SM_PAR    (SM_B + 8 * 4 * 32 * 16)   // +16384
#define SM_BYTES  (SM_PAR + 136 * 4)    // 199712 < 232448

__device__ uint2 g_xh[MAX_NODES * 32];  // x in fp16: 32 x uint2 (=128 fp16) per row

__device__ __forceinline__ uint32_t smem_u32(const void* p) {
    uint32_t a;
    asm("{ .reg .u64 t; cvta.to.shared.u64 t, %1; cvt.u32.u64 %0, t; }" : "=r"(a) : "l"(p));
    return a;
}
__device__ __forceinline__ uint32_t lds32(uint32_t addr) {
    uint32_t v;
    asm volatile("ld.shared.b32 %0, [%1];" : "=r"(v) : "r"(addr));
    return v;
}
__device__ __forceinline__ uint4 lds128(uint32_t addr) {
    uint4 v;
    asm volatile("ld.shared.v4.b32 {%0,%1,%2,%3}, [%4];"
                 : "=r"(v.x), "=r"(v.y), "=r"(v.z), "=r"(v.w) : "r"(addr));
    return v;
}
__device__ __forceinline__ void sts64(uint32_t addr, uint2 v) {
    asm volatile("st.shared.v2.b32 [%0], {%1,%2};" :: "r"(addr), "r"(v.x), "r"(v.y));
}

// pack two f32 into f16x2 word: lo arg -> lower half, hi arg -> upper half.
__device__ __forceinline__ uint32_t pack_f16x2(float lo, float hi) {
    uint32_t u;
    asm("cvt.rn.f16x2.f32 %0, %1, %2;" : "=r"(u) : "f"(hi), "f"(lo));
    return u;
}
// |a - b| on packed fp16x2
__device__ __forceinline__ uint32_t habs_diff2(uint32_t a, uint32_t b) {
    __half2 d = __habs2(__hsub2(*(__half2*)&a, *(__half2*)&b));
    return *(uint32_t*)&d;
}

__device__ __forceinline__ void mma_f16(float* c, const uint32_t* a,
                                        uint32_t b0, uint32_t b1) {
    asm volatile(
        "mma.sync.aligned.m16n8k16.row.col.f32.f16.f16.f32 "
        "{%0,%1,%2,%3}, {%4,%5,%6,%7}, {%8,%9}, {%0,%1,%2,%3};"
        : "+f"(c[0]), "+f"(c[1]), "+f"(c[2]), "+f"(c[3])
        : "r"(a[0]), "r"(a[1]), "r"(a[2]), "r"(a[3]), "r"(b0), "r"(b1));
}

// Load one m16k16 A fragment (4 u32): rows g, g+8; col words 2t.., 2t+8..
__device__ __forceinline__ void ld_afrag(uint32_t* f, uint32_t base, int g, uint32_t cb) {
    uint32_t r0 = base + (uint32_t)g * A_ROW_B + cb;
    uint32_t r8 = r0 + 8 * A_ROW_B;
    f[0] = lds32(r0);
    f[1] = lds32(r8);
    f[2] = lds32(r0 + 16);
    f[3] = lds32(r8 + 16);
}

// ---- prepass: convert x (f32) -> fp16 rows in g_xh ----
__global__ void convert_x_kernel(const float4* __restrict__ x4, int n_quads) {
    int i = blockIdx.x * blockDim.x + threadIdx.x;   // one float4 -> one uint2
    if (i < n_quads) {
        float4 v = x4[i];
        g_xh[i] = make_uint2(pack_f16x2(v.x, v.y), pack_f16x2(v.z, v.w));
    }
}

__global__ void __launch_bounds__(THREADS, 1) edge_mlp(
    const int* __restrict__ idx32,
    const float* __restrict__ W1, const float* __restrict__ b1,
    const float* __restrict__ W2, const float* __restrict__ b2,
    float* __restrict__ out, int n_edges, int n_nodes,
    int n_tiles, int n_warps_total)
{
    extern __shared__ char smem[];
    const uint32_t sb = smem_u32(smem);
    const int tid = threadIdx.x, wid = tid >> 5, lid = tid & 31;
    float* par = (float*)(smem + SM_PAR);
    int* flag = (int*)(par + 132);

    // ---- inline index-dtype detection (warp 0): int64 nonneg => all high
    // words zero; int32 => "high words" are random indices, OR != 0 w.h.p. ----
    if (wid == 0) {
        int j = lid < n_edges ? lid : 0;
        int v = idx32[2 * j + 1];
        v = __reduce_or_sync(0xffffffffu, v);
        if (lid == 0) *flag = (v == 0) ? 1 : 0;
    }

    // ---- one-time: stage W1 as per-lane fp16 B fragments, 2 ns per uint4 ----
    // Lane L (g=L/4, t=L%4), tile (ks, ns): frag = { {W1[16ks+2t][8ns+g],
    // W1[16ks+2t+1][...]}, k rows +8,+9 }. uint4 packs ns=2p and ns=2p+1.
    for (int e = tid; e < 2048; e += THREADS) {
        int tile = e >> 5, lane = e & 31;
        int ks = tile >> 3, ns = tile & 7;
        int g = lane >> 2, t = lane & 3;
        int col = ns * 8 + g;
        int kb = ks * 16 + 2 * t;
        uint32_t f0 = pack_f16x2(W1[(kb    ) * HID + col], W1[(kb + 1) * HID + col]);
        uint32_t f1 = pack_f16x2(W1[(kb + 8) * HID + col], W1[(kb + 9) * HID + col]);
        uint32_t addr = sb + SM_B + (uint32_t)(((ks * 4 + (ns >> 1)) * 32 + lane) * 16
                                               + (ns & 1) * 8);
        sts64(addr, make_uint2(f0, f1));
    }
    if (tid < HID)            par[tid] = b1[tid];
    else if (tid < 2 * HID)   par[tid] = W2[tid - HID];
    if (tid == 2 * HID)       par[128] = b2[0];
    __syncthreads();

    const int is64 = *flag;
    const uint32_t aw = sb + SM_A + (uint32_t)wid * A_WARP_B;
    const int g2 = lid >> 2, t4 = lid & 3;

    // ---- persistent warp-independent tile loop ----
    for (int tile = blockIdx.x * WPC + wid; tile < n_tiles; tile += n_warps_total) {
        const int e0 = tile * TILE_E;
        int n0v = 0, n1v = 0;
        {
            int eg = e0 + lid;
            if (eg < n_edges) {
                if (is64) {
                    n0v = idx32[2 * eg];
                    n1v = idx32[2 * (n_edges + eg)];
                } else {
                    n0v = idx32[eg];
                    n1v = idx32[n_edges + eg];
                }
            }
            if ((unsigned)n0v >= (unsigned)n_nodes) n0v = 0;
            if ((unsigned)n1v >= (unsigned)n_nodes) n1v = 0;
        }
        __syncwarp();

        // gather fp16 rows + |diff| (half2) -> A rows. 256B/row, coalesced.
        #pragma unroll 4
        for (int t = 0; t < TILE_E; t++) {
            int r0 = __shfl_sync(0xffffffffu, n0v, t);
            int r1 = __shfl_sync(0xffffffffu, n1v, t);
            uint2 a = __ldg(&g_xh[r0 * 32 + lid]);
            uint2 b = __ldg(&g_xh[r1 * 32 + lid]);
            uint2 d = make_uint2(habs_diff2(a.x, b.x), habs_diff2(a.y, b.y));
            sts64(aw + (uint32_t)t * A_ROW_B + (uint32_t)lid * 8, d);
        }
        __syncwarp();

        // ---- MMA: 2 m16-tiles x 8 n8-tiles x 8 k16-steps, single-term.
        //      B fragment loaded once, shared by both m-tiles. ----
        float acc[2][8][4];
        #pragma unroll
        for (int mt = 0; mt < 2; mt++)
            #pragma unroll
            for (int ns = 0; ns < 8; ns++)
                #pragma unroll
                for (int c = 0; c < 4; c++) acc[mt][ns][c] = 0.f;

        #pragma unroll 2
        for (int ks = 0; ks < 8; ks++) {
            uint32_t a0[4], a1[4];
            const uint32_t cb = (uint32_t)(ks * 32 + t4 * 4);
            ld_afrag(a0, aw, g2, cb);
            ld_afrag(a1, aw + 16 * A_ROW_B, g2, cb);
            const uint32_t bbase = sb + SM_B + (uint32_t)(ks * 2048 + lid * 16);
            #pragma unroll
            for (int np = 0; np < 4; np++) {
                uint4 B = lds128(bbase + np * 512);
                mma_f16(acc[0][2 * np],     a0, B.x, B.y);
                mma_f16(acc[1][2 * np],     a1, B.x, B.y);
                mma_f16(acc[0][2 * np + 1], a0, B.z, B.w);
                mma_f16(acc[1][2 * np + 1], a1, B.z, B.w);
            }
        }

        // ---- epilogue: h=relu(acc+b1); z=h.W2+b2; out=sigmoid(z) ----
        // D frag: c0=(g,2t) c1=(g,2t+1) c2=(g+8,2t) c3=(g+8,2t+1)
        #pragma unroll
        for (int mt = 0; mt < 2; mt++) {
            float za = par[128], zb = par[128];
            #pragma unroll
            for (int ns = 0; ns < 8; ns++) {
                int c0 = ns * 8 + 2 * t4, c1 = c0 + 1;
                float h;
                h = fmaxf(acc[mt][ns][0] + par[c0], 0.f); za = fmaf(h, par[64 + c0], za);
                h = fmaxf(acc[mt][ns][1] + par[c1], 0.f); za = fmaf(h, par[64 + c1], za);
                h = fmaxf(acc[mt][ns][2] + par[c0], 0.f); zb = fmaf(h, par[64 + c0], zb);
                h = fmaxf(acc[mt][ns][3] + par[c1], 0.f); zb = fmaf(h, par[64 + c1], zb);
            }
            za += __shfl_xor_sync(0xffffffffu, za, 1);
            za += __shfl_xor_sync(0xffffffffu, za, 2);
            zb += __shfl_xor_sync(0xffffffffu, zb, 1);
            zb += __shfl_xor_sync(0xffffffffu, zb, 2);
            if (t4 == 0) {
                int ea = e0 + mt * 16 + g2;
                int eb = ea + 8;
                if (ea < n_edges) out[ea] = 1.f / (1.f + __expf(-za));
                if (eb < n_edges) out[eb] = 1.f / (1.f + __expf(-zb));
            }
        }
        __syncwarp();
    }
}

extern "C" void kernel_launch(void* const* d_in, const int* in_sizes, int n_in,
                              void* d_out, int out_size) {
    const float* x   = (const float*)d_in[0];
    const int*   idx = (const int*)d_in[1];
    const float* W1  = (const float*)d_in[2];
    const float* b1  = (const float*)d_in[3];
    const float* W2  = (const float*)d_in[4];
    const float* b2  = (const float*)d_in[5];
    float*       out = (float*)d_out;

    int n_edges = in_sizes[1] / 2;                 // indices is [2, n_edges]
    int n_nodes = in_sizes[0] / D_FEAT;            // x is [n_nodes, 128] f32
    if (n_nodes > MAX_NODES) n_nodes = MAX_NODES;
    int n_tiles = (n_edges + TILE_E - 1) / TILE_E;

    int sms = 148;
    cudaDeviceGetAttribute(&sms, cudaDevAttrMultiProcessorCount, 0);

    int n_quads = n_nodes * 32;                    // one float4 per uint2 row chunk
    convert_x_kernel<<<(n_quads + 255) / 256, 256>>>((const float4*)x, n_quads);

    cudaFuncSetAttribute(edge_mlp, cudaFuncAttributeMaxDynamicSharedMemorySize, SM_BYTES);
    edge_mlp<<<sms, THREADS, SM_BYTES>>>(idx, W1, b1, W2, b2,
                                         out, n_edges, n_nodes, n_tiles, sms * WPC);
}

// round 12
// speedup vs baseline: 1.2565x; 1.2565x over previous
#include <cuda_runtime.h>
#include <cuda_fp16.h>
#include <cstdint>

// ============================================================================
// EdgeCompute: out[e] = sigmoid(relu(|x[i0[e]] - x[i1[e]]| @ W1 + b1) @ W2 + b2)
// R11: WPC 28->32 (1024 threads, occ 50%) via __launch_bounds__(1024,1)
// forcing <=64 regs/thread (audit: acc 32 + frags 8 + control ~20 = ~60).
// R10 lesson locked in: occupancy dominates wf/edge on this kernel -> keep
// TILE_E=16. Persistent kernel, warp-independent tiles, x pre-converted to
// fp16 (halved gather), pure fp16 single-term m16n8k16 (rel_err ~1e-4).
// Inline index-dtype detection (int32 vs JAX-demoted int64).
// ============================================================================

#define D_FEAT 128
#define HID 64
#define WPC 32
#define THREADS (WPC * 32)
#define TILE_E 16
#define MAX_NODES 16384

#define A_ROW_B   272                   // 128 fp16 + 16B pad -> conflict-free frags
#define A_WARP_B  (TILE_E * A_ROW_B)    // 4352
#define SM_A      0
#define SM_B      (WPC * A_WARP_B)      // 139264: 8 ks x 4 ns-pairs x 32 lanes x uint4
#define SM_PAR    (SM_B + 8 * 4 * 32 * 16)   // +16384
#define SM_BYTES  (SM_PAR + 136 * 4)    // 156192 < 232448

__device__ uint2 g_xh[MAX_NODES * 32];  // x in fp16: 32 x uint2 (=128 fp16) per row

__device__ __forceinline__ uint32_t smem_u32(const void* p) {
    uint32_t a;
    asm("{ .reg .u64 t; cvta.to.shared.u64 t, %1; cvt.u32.u64 %0, t; }" : "=r"(a) : "l"(p));
    return a;
}
__device__ __forceinline__ uint32_t lds32(uint32_t addr) {
    uint32_t v;
    asm volatile("ld.shared.b32 %0, [%1];" : "=r"(v) : "r"(addr));
    return v;
}
__device__ __forceinline__ uint4 lds128(uint32_t addr) {
    uint4 v;
    asm volatile("ld.shared.v4.b32 {%0,%1,%2,%3}, [%4];"
                 : "=r"(v.x), "=r"(v.y), "=r"(v.z), "=r"(v.w) : "r"(addr));
    return v;
}
__device__ __forceinline__ void sts64(uint32_t addr, uint2 v) {
    asm volatile("st.shared.v2.b32 [%0], {%1,%2};" :: "r"(addr), "r"(v.x), "r"(v.y));
}

// pack two f32 into f16x2 word: lo arg -> lower half, hi arg -> upper half.
__device__ __forceinline__ uint32_t pack_f16x2(float lo, float hi) {
    uint32_t u;
    asm("cvt.rn.f16x2.f32 %0, %1, %2;" : "=r"(u) : "f"(hi), "f"(lo));
    return u;
}
// |a - b| on packed fp16x2
__device__ __forceinline__ uint32_t habs_diff2(uint32_t a, uint32_t b) {
    __half2 d = __habs2(__hsub2(*(__half2*)&a, *(__half2*)&b));
    return *(uint32_t*)&d;
}

__device__ __forceinline__ void mma_f16(float* c, const uint32_t* a,
                                        uint32_t b0, uint32_t b1) {
    asm volatile(
        "mma.sync.aligned.m16n8k16.row.col.f32.f16.f16.f32 "
        "{%0,%1,%2,%3}, {%4,%5,%6,%7}, {%8,%9}, {%0,%1,%2,%3};"
        : "+f"(c[0]), "+f"(c[1]), "+f"(c[2]), "+f"(c[3])
        : "r"(a[0]), "r"(a[1]), "r"(a[2]), "r"(a[3]), "r"(b0), "r"(b1));
}

// Load one m16k16 A fragment (4 u32): rows g, g+8; col words 2t.., 2t+8..
__device__ __forceinline__ void ld_afrag(uint32_t* f, uint32_t base, int g, uint32_t cb) {
    uint32_t r0 = base + (uint32_t)g * A_ROW_B + cb;
    uint32_t r8 = r0 + 8 * A_ROW_B;
    f[0] = lds32(r0);
    f[1] = lds32(r8);
    f[2] = lds32(r0 + 16);
    f[3] = lds32(r8 + 16);
}

// ---- prepass: convert x (f32) -> fp16 rows in g_xh ----
__global__ void convert_x_kernel(const float4* __restrict__ x4, int n_quads) {
    int i = blockIdx.x * blockDim.x + threadIdx.x;   // one float4 -> one uint2
    if (i < n_quads) {
        float4 v = x4[i];
        g_xh[i] = make_uint2(pack_f16x2(v.x, v.y), pack_f16x2(v.z, v.w));
    }
}

__global__ void __launch_bounds__(THREADS, 1) edge_mlp(
    const int* __restrict__ idx32,
    const float* __restrict__ W1, const float* __restrict__ b1,
    const float* __restrict__ W2, const float* __restrict__ b2,
    float* __restrict__ out, int n_edges, int n_nodes,
    int n_tiles, int n_warps_total)
{
    extern __shared__ char smem[];
    const uint32_t sb = smem_u32(smem);
    const int tid = threadIdx.x, wid = tid >> 5, lid = tid & 31;
    float* par = (float*)(smem + SM_PAR);
    int* flag = (int*)(par + 132);

    // ---- inline index-dtype detection (warp 0): int64 nonneg => all high
    // words zero; int32 => "high words" are random indices, OR != 0 w.h.p. ----
    if (wid == 0) {
        int j = lid < n_edges ? lid : 0;
        int v = idx32[2 * j + 1];
        v = __reduce_or_sync(0xffffffffu, v);
        if (lid == 0) *flag = (v == 0) ? 1 : 0;
    }

    // ---- one-time: stage W1 as per-lane fp16 B fragments, 2 ns per uint4 ----
    // Lane L (g=L/4, t=L%4), tile (ks, ns): frag = { {W1[16ks+2t][8ns+g],
    // W1[16ks+2t+1][...]}, k rows +8,+9 }. uint4 packs ns=2p and ns=2p+1.
    for (int e = tid; e < 2048; e += THREADS) {
        int tile = e >> 5, lane = e & 31;
        int ks = tile >> 3, ns = tile & 7;
        int g = lane >> 2, t = lane & 3;
        int col = ns * 8 + g;
        int kb = ks * 16 + 2 * t;
        uint32_t f0 = pack_f16x2(W1[(kb    ) * HID + col], W1[(kb + 1) * HID + col]);
        uint32_t f1 = pack_f16x2(W1[(kb + 8) * HID + col], W1[(kb + 9) * HID + col]);
        uint32_t addr = sb + SM_B + (uint32_t)(((ks * 4 + (ns >> 1)) * 32 + lane) * 16
                                               + (ns & 1) * 8);
        sts64(addr, make_uint2(f0, f1));
    }
    if (tid < HID)            par[tid] = b1[tid];
    else if (tid < 2 * HID)   par[tid] = W2[tid - HID];
    if (tid == 2 * HID)       par[128] = b2[0];
    __syncthreads();

    const int is64 = *flag;
    const uint32_t aw = sb + SM_A + (uint32_t)wid * A_WARP_B;
    const int g2 = lid >> 2, t4 = lid & 3;

    // ---- persistent warp-independent tile loop ----
    for (int tile = blockIdx.x * WPC + wid; tile < n_tiles; tile += n_warps_total) {
        const int e0 = tile * TILE_E;
        int n0v = 0, n1v = 0;
        {
            int eg = e0 + (lid & 15);
            if (eg < n_edges) {
                if (is64) {
                    n0v = idx32[2 * eg];
                    n1v = idx32[2 * (n_edges + eg)];
                } else {
                    n0v = idx32[eg];
                    n1v = idx32[n_edges + eg];
                }
            }
            if ((unsigned)n0v >= (unsigned)n_nodes) n0v = 0;
            if ((unsigned)n1v >= (unsigned)n_nodes) n1v = 0;
        }
        __syncwarp();

        // gather fp16 rows + |diff| (half2) -> A rows. 256B/row, coalesced.
        #pragma unroll 4
        for (int t = 0; t < TILE_E; t++) {
            int r0 = __shfl_sync(0xffffffffu, n0v, t);
            int r1 = __shfl_sync(0xffffffffu, n1v, t);
            uint2 a = __ldg(&g_xh[r0 * 32 + lid]);
            uint2 b = __ldg(&g_xh[r1 * 32 + lid]);
            uint2 d = make_uint2(habs_diff2(a.x, b.x), habs_diff2(a.y, b.y));
            sts64(aw + (uint32_t)t * A_ROW_B + (uint32_t)lid * 8, d);
        }
        __syncwarp();

        // ---- MMA: 1 m16-tile x 8 n8-tiles x 8 k16-steps, single-term ----
        float acc[8][4];
        #pragma unroll
        for (int ns = 0; ns < 8; ns++)
            #pragma unroll
            for (int c = 0; c < 4; c++) acc[ns][c] = 0.f;

        #pragma unroll 2
        for (int ks = 0; ks < 8; ks++) {
            uint32_t a0[4];
            const uint32_t cb = (uint32_t)(ks * 32 + t4 * 4);
            ld_afrag(a0, aw, g2, cb);
            const uint32_t bbase = sb + SM_B + (uint32_t)(ks * 2048 + lid * 16);
            #pragma unroll
            for (int np = 0; np < 4; np++) {
                uint4 B = lds128(bbase + np * 512);
                mma_f16(acc[2 * np],     a0, B.x, B.y);
                mma_f16(acc[2 * np + 1], a0, B.z, B.w);
            }
        }

        // ---- epilogue: h=relu(acc+b1); z=h.W2+b2; out=sigmoid(z) ----
        // D frag: c0=(g,2t) c1=(g,2t+1) c2=(g+8,2t) c3=(g+8,2t+1)
        float za = par[128], zb = par[128];
        #pragma unroll
        for (int ns = 0; ns < 8; ns++) {
            int c0 = ns * 8 + 2 * t4, c1 = c0 + 1;
            float h;
            h = fmaxf(acc[ns][0] + par[c0], 0.f); za = fmaf(h, par[64 + c0], za);
            h = fmaxf(acc[ns][1] + par[c1], 0.f); za = fmaf(h, par[64 + c1], za);
            h = fmaxf(acc[ns][2] + par[c0], 0.f); zb = fmaf(h, par[64 + c0], zb);
            h = fmaxf(acc[ns][3] + par[c1], 0.f); zb = fmaf(h, par[64 + c1], zb);
        }
        za += __shfl_xor_sync(0xffffffffu, za, 1);
        za += __shfl_xor_sync(0xffffffffu, za, 2);
        zb += __shfl_xor_sync(0xffffffffu, zb, 1);
        zb += __shfl_xor_sync(0xffffffffu, zb, 2);
        if (t4 == 0) {
            int ea = e0 + g2;
            int eb = ea + 8;
            if (ea < n_edges) out[ea] = 1.f / (1.f + __expf(-za));
            if (eb < n_edges) out[eb] = 1.f / (1.f + __expf(-zb));
        }
        __syncwarp();
    }
}

extern "C" void kernel_launch(void* const* d_in, const int* in_sizes, int n_in,
                              void* d_out, int out_size) {
    const float* x   = (const float*)d_in[0];
    const int*   idx = (const int*)d_in[1];
    const float* W1  = (const float*)d_in[2];
    const float* b1  = (const float*)d_in[3];
    const float* W2  = (const float*)d_in[4];
    const float* b2  = (const float*)d_in[5];
    float*       out = (float*)d_out;

    int n_edges = in_sizes[1] / 2;                 // indices is [2, n_edges]
    int n_nodes = in_sizes[0] / D_FEAT;            // x is [n_nodes, 128] f32
    if (n_nodes > MAX_NODES) n_nodes = MAX_NODES;
    int n_tiles = (n_edges + TILE_E - 1) / TILE_E;

    int sms = 148;
    cudaDeviceGetAttribute(&sms, cudaDevAttrMultiProcessorCount, 0);

    int n_quads = n_nodes * 32;                    // one float4 per uint2 row chunk
    convert_x_kernel<<<(n_quads + 255) / 256, 256>>>((const float4*)x, n_quads);

    cudaFuncSetAttribute(edge_mlp, cudaFuncAttributeMaxDynamicSharedMemorySize, SM_BYTES);
    edge_mlp<<<sms, THREADS, SM_BYTES>>>(idx, W1, b1, W2, b2,
                                         out, n_edges, n_nodes, n_tiles, sms * WPC);
}

// round 13
// speedup vs baseline: 1.3431x; 1.0689x over previous
#include <cuda_runtime.h>
#include <cuda_fp16.h>
#include <cstdint>

// ============================================================================
// EdgeCompute: out[e] = sigmoid(relu(|x[i0[e]] - x[i1[e]]| @ W1 + b1) @ W2 + b2)
// R12: warp-PAIR cooperative 32-edge tiles, ns split 4/4 between the pair.
// Register-neutral (acc stays 32 floats) so occupancy holds at 32 warps/SM,
// while B-fragment traffic halves: 14 L1 wavefronts/edge vs 18.
// Pair sync via named barriers (id = pair 0..15, 64 threads); epilogue
// combines per-warp partial dot-products through a SMEM pair buffer.
// x pre-converted to fp16 (halved gather), pure fp16 single-term m16n8k16.
// Inline index-dtype detection (int32 vs JAX-demoted int64).
// ============================================================================

#define D_FEAT 128
#define HID 64
#define WPC 32
#define THREADS (WPC * 32)
#define N_PAIRS (WPC / 2)
#define TILE_E 32
#define MAX_NODES 16384

#define A_ROW_B   272                   // 128 fp16 + 16B pad -> conflict-free frags
#define A_PAIR_B  (TILE_E * A_ROW_B)    // 8704 per pair
#define SM_A      0
#define SM_B      (N_PAIRS * A_PAIR_B)  // 139264: 8 ks x 4 ns-pairs x 32 lanes x uint4
#define SM_PAR    (SM_B + 8 * 4 * 32 * 16)   // +16384 -> 155648
#define SM_PB     (SM_PAR + 136 * 4)    // pair partial buffers: 16 x 64 floats
#define SM_BYTES  (SM_PB + N_PAIRS * 64 * 4) // 160288 < 232448

__device__ uint2 g_xh[MAX_NODES * 32];  // x in fp16: 32 x uint2 (=128 fp16) per row

__device__ __forceinline__ uint32_t smem_u32(const void* p) {
    uint32_t a;
    asm("{ .reg .u64 t; cvta.to.shared.u64 t, %1; cvt.u32.u64 %0, t; }" : "=r"(a) : "l"(p));
    return a;
}
__device__ __forceinline__ uint32_t lds32(uint32_t addr) {
    uint32_t v;
    asm volatile("ld.shared.b32 %0, [%1];" : "=r"(v) : "r"(addr));
    return v;
}
__device__ __forceinline__ uint4 lds128(uint32_t addr) {
    uint4 v;
    asm volatile("ld.shared.v4.b32 {%0,%1,%2,%3}, [%4];"
                 : "=r"(v.x), "=r"(v.y), "=r"(v.z), "=r"(v.w) : "r"(addr));
    return v;
}
__device__ __forceinline__ void sts64(uint32_t addr, uint2 v) {
    asm volatile("st.shared.v2.b32 [%0], {%1,%2};" :: "r"(addr), "r"(v.x), "r"(v.y));
}
#define PAIR_BAR(id) asm volatile("bar.sync %0, 64;" :: "r"(id) : "memory")

// pack two f32 into f16x2 word: lo arg -> lower half, hi arg -> upper half.
__device__ __forceinline__ uint32_t pack_f16x2(float lo, float hi) {
    uint32_t u;
    asm("cvt.rn.f16x2.f32 %0, %1, %2;" : "=r"(u) : "f"(hi), "f"(lo));
    return u;
}
// |a - b| on packed fp16x2
__device__ __forceinline__ uint32_t habs_diff2(uint32_t a, uint32_t b) {
    __half2 d = __habs2(__hsub2(*(__half2*)&a, *(__half2*)&b));
    return *(uint32_t*)&d;
}

__device__ __forceinline__ void mma_f16(float* c, const uint32_t* a,
                                        uint32_t b0, uint32_t b1) {
    asm volatile(
        "mma.sync.aligned.m16n8k16.row.col.f32.f16.f16.f32 "
        "{%0,%1,%2,%3}, {%4,%5,%6,%7}, {%8,%9}, {%0,%1,%2,%3};"
        : "+f"(c[0]), "+f"(c[1]), "+f"(c[2]), "+f"(c[3])
        : "r"(a[0]), "r"(a[1]), "r"(a[2]), "r"(a[3]), "r"(b0), "r"(b1));
}

// Load one m16k16 A fragment (4 u32): rows g, g+8; col words 2t.., 2t+8..
__device__ __forceinline__ void ld_afrag(uint32_t* f, uint32_t base, int g, uint32_t cb) {
    uint32_t r0 = base + (uint32_t)g * A_ROW_B + cb;
    uint32_t r8 = r0 + 8 * A_ROW_B;
    f[0] = lds32(r0);
    f[1] = lds32(r8);
    f[2] = lds32(r0 + 16);
    f[3] = lds32(r8 + 16);
}

// ---- prepass: convert x (f32) -> fp16 rows in g_xh ----
__global__ void convert_x_kernel(const float4* __restrict__ x4, int n_quads) {
    int i = blockIdx.x * blockDim.x + threadIdx.x;   // one float4 -> one uint2
    if (i < n_quads) {
        float4 v = x4[i];
        g_xh[i] = make_uint2(pack_f16x2(v.x, v.y), pack_f16x2(v.z, v.w));
    }
}

__global__ void __launch_bounds__(THREADS, 1) edge_mlp(
    const int* __restrict__ idx32,
    const float* __restrict__ W1, const float* __restrict__ b1,
    const float* __restrict__ W2, const float* __restrict__ b2,
    float* __restrict__ out, int n_edges, int n_nodes,
    int n_tiles, int n_pairs_total)
{
    extern __shared__ char smem[];
    const uint32_t sb = smem_u32(smem);
    const int tid = threadIdx.x, wid = tid >> 5, lid = tid & 31;
    float* par = (float*)(smem + SM_PAR);
    int* flag = (int*)(par + 132);
    float* pb  = (float*)(smem + SM_PB);

    // ---- inline index-dtype detection (warp 0): int64 nonneg => all high
    // words zero; int32 => "high words" are random indices, OR != 0 w.h.p. ----
    if (wid == 0) {
        int j = lid < n_edges ? lid : 0;
        int v = idx32[2 * j + 1];
        v = __reduce_or_sync(0xffffffffu, v);
        if (lid == 0) *flag = (v == 0) ? 1 : 0;
    }

    // ---- one-time: stage W1 as per-lane fp16 B fragments, 2 ns per uint4 ----
    // Lane L (g=L/4, t=L%4), tile (ks, ns): frag = { {W1[16ks+2t][8ns+g],
    // W1[16ks+2t+1][...]}, k rows +8,+9 }. uint4 packs ns=2p and ns=2p+1.
    for (int e = tid; e < 2048; e += THREADS) {
        int tile = e >> 5, lane = e & 31;
        int ks = tile >> 3, ns = tile & 7;
        int g = lane >> 2, t = lane & 3;
        int col = ns * 8 + g;
        int kb = ks * 16 + 2 * t;
        uint32_t f0 = pack_f16x2(W1[(kb    ) * HID + col], W1[(kb + 1) * HID + col]);
        uint32_t f1 = pack_f16x2(W1[(kb + 8) * HID + col], W1[(kb + 9) * HID + col]);
        uint32_t addr = sb + SM_B + (uint32_t)(((ks * 4 + (ns >> 1)) * 32 + lane) * 16
                                               + (ns & 1) * 8);
        sts64(addr, make_uint2(f0, f1));
    }
    if (tid < HID)            par[tid] = b1[tid];
    else if (tid < 2 * HID)   par[tid] = W2[tid - HID];
    if (tid == 2 * HID)       par[128] = b2[0];
    __syncthreads();

    const int is64 = *flag;
    const int pair = wid >> 1, pid = wid & 1;
    const uint32_t aw = sb + SM_A + (uint32_t)pair * A_PAIR_B;
    const int g2 = lid >> 2, t4 = lid & 3;
    float* mypb = pb + pair * 64;

    // ---- persistent pair-cooperative tile loop ----
    for (int tile = blockIdx.x * N_PAIRS + pair; tile < n_tiles; tile += n_pairs_total) {
        const int e0 = tile * TILE_E;
        // this warp owns edges [e0 + pid*16, e0 + pid*16 + 16)
        int n0v = 0, n1v = 0;
        {
            int eg = e0 + pid * 16 + (lid & 15);
            if (eg < n_edges) {
                if (is64) {
                    n0v = idx32[2 * eg];
                    n1v = idx32[2 * (n_edges + eg)];
                } else {
                    n0v = idx32[eg];
                    n1v = idx32[n_edges + eg];
                }
            }
            if ((unsigned)n0v >= (unsigned)n_nodes) n0v = 0;
            if ((unsigned)n1v >= (unsigned)n_nodes) n1v = 0;
        }
        __syncwarp();

        // gather fp16 rows + |diff| (half2) -> A rows pid*16 .. pid*16+15
        #pragma unroll 4
        for (int t = 0; t < 16; t++) {
            int r0 = __shfl_sync(0xffffffffu, n0v, t);
            int r1 = __shfl_sync(0xffffffffu, n1v, t);
            uint2 a = __ldg(&g_xh[r0 * 32 + lid]);
            uint2 b = __ldg(&g_xh[r1 * 32 + lid]);
            uint2 d = make_uint2(habs_diff2(a.x, b.x), habs_diff2(a.y, b.y));
            sts64(aw + (uint32_t)(pid * 16 + t) * A_ROW_B + (uint32_t)lid * 8, d);
        }
        PAIR_BAR(pair);   // A tile complete (and prior tile's pb reads done)

        // ---- MMA: 2 m16-tiles x my 4 ns-tiles x 8 k16-steps ----
        float acc[2][4][4];
        #pragma unroll
        for (int mt = 0; mt < 2; mt++)
            #pragma unroll
            for (int ns = 0; ns < 4; ns++)
                #pragma unroll
                for (int c = 0; c < 4; c++) acc[mt][ns][c] = 0.f;

        #pragma unroll 2
        for (int ks = 0; ks < 8; ks++) {
            uint32_t a0[4], a1[4];
            const uint32_t cb = (uint32_t)(ks * 32 + t4 * 4);
            ld_afrag(a0, aw, g2, cb);
            ld_afrag(a1, aw + 16 * A_ROW_B, g2, cb);
            const uint32_t bbase = sb + SM_B
                + (uint32_t)(ks * 2048 + (2 * pid) * 512 + lid * 16);
            #pragma unroll
            for (int i = 0; i < 2; i++) {
                uint4 B = lds128(bbase + i * 512);
                mma_f16(acc[0][2 * i],     a0, B.x, B.y);
                mma_f16(acc[1][2 * i],     a1, B.x, B.y);
                mma_f16(acc[0][2 * i + 1], a0, B.z, B.w);
                mma_f16(acc[1][2 * i + 1], a1, B.z, B.w);
            }
        }

        // ---- epilogue: partial z over my 32 hidden cols, per (mt, row) ----
        // D frag rows: c0/c1 -> row g, c2/c3 -> row g+8.
        #pragma unroll
        for (int mt = 0; mt < 2; mt++) {
            float za = 0.f, zb = 0.f;
            #pragma unroll
            for (int i = 0; i < 4; i++) {
                int nsg = 4 * pid + i;
                int c0 = nsg * 8 + 2 * t4, c1 = c0 + 1;
                float h;
                h = fmaxf(acc[mt][i][0] + par[c0], 0.f); za = fmaf(h, par[64 + c0], za);
                h = fmaxf(acc[mt][i][1] + par[c1], 0.f); za = fmaf(h, par[64 + c1], za);
                h = fmaxf(acc[mt][i][2] + par[c0], 0.f); zb = fmaf(h, par[64 + c0], zb);
                h = fmaxf(acc[mt][i][3] + par[c1], 0.f); zb = fmaf(h, par[64 + c1], zb);
            }
            za += __shfl_xor_sync(0xffffffffu, za, 1);
            za += __shfl_xor_sync(0xffffffffu, za, 2);
            zb += __shfl_xor_sync(0xffffffffu, zb, 1);
            zb += __shfl_xor_sync(0xffffffffu, zb, 2);
            if (t4 == 0) {
                mypb[pid * 32 + mt * 16 + g2]     = za;   // rows mt*16 + g2
                mypb[pid * 32 + mt * 16 + 8 + g2] = zb;   // rows mt*16 + 8 + g2
            }
        }
        PAIR_BAR(pair);   // partials visible

        // combine: this warp finalizes rows of m-block mt = pid
        if (lid < 16) {
            float z = mypb[pid * 16 + lid] + mypb[32 + pid * 16 + lid] + par[128];
            int e = e0 + pid * 16 + lid;
            if (e < n_edges) out[e] = 1.f / (1.f + __expf(-z));
        }
        __syncwarp();
    }
}

extern "C" void kernel_launch(void* const* d_in, const int* in_sizes, int n_in,
                              void* d_out, int out_size) {
    const float* x   = (const float*)d_in[0];
    const int*   idx = (const int*)d_in[1];
    const float* W1  = (const float*)d_in[2];
    const float* b1  = (const float*)d_in[3];
    const float* W2  = (const float*)d_in[4];
    const float* b2  = (const float*)d_in[5];
    float*       out = (float*)d_out;

    int n_edges = in_sizes[1] / 2;                 // indices is [2, n_edges]
    int n_nodes = in_sizes[0] / D_FEAT;            // x is [n_nodes, 128] f32
    if (n_nodes > MAX_NODES) n_nodes = MAX_NODES;
    int n_tiles = (n_edges + TILE_E - 1) / TILE_E;

    int sms = 148;
    cudaDeviceGetAttribute(&sms, cudaDevAttrMultiProcessorCount, 0);

    int n_quads = n_nodes * 32;                    // one float4 per uint2 row chunk
    convert_x_kernel<<<(n_quads + 255) / 256, 256>>>((const float4*)x, n_quads);

    cudaFuncSetAttribute(edge_mlp, cudaFuncAttributeMaxDynamicSharedMemorySize, SM_BYTES);
    edge_mlp<<<sms, THREADS, SM_BYTES>>>(idx, W1, b1, W2, b2,
                                         out, n_edges, n_nodes, n_tiles,
                                         sms * N_PAIRS);
}

// round 14
// speedup vs baseline: 1.3899x; 1.0348x over previous
#include <cuda_runtime.h>
#include <cuda_fp16.h>
#include <cstdint>

// ============================================================================
// EdgeCompute: out[e] = sigmoid(relu(|x[i0[e]] - x[i1[e]]| @ W1 + b1) @ W2 + b2)
// R13: latency shaping on the R12 warp-pair kernel (traffic & math unchanged):
//  - 8 edges' gather ldgs hoisted ABOVE the first pair-barrier (L2 latency
//    overlaps the rendezvous wait; acc regs are dead there).
//  - combine/output deferred one tile: runs right after bar#1 of the next
//    tile, where partner's pb write is already ordered -> no dedicated wait.
// Pair protocol: [idx+ldg8 | barA | combine(t-1) | sts8 | ldg+sts8 | barB |
// mma | pb-write]; drain bar + combine after the loop.
// 32 warps/CTA, pure fp16 single-term m16n8k16, x pre-converted to fp16.
// ============================================================================

#define D_FEAT 128
#define HID 64
#define WPC 32
#define THREADS (WPC * 32)
#define N_PAIRS (WPC / 2)
#define TILE_E 32
#define MAX_NODES 16384

#define A_ROW_B   272                   // 128 fp16 + 16B pad -> conflict-free frags
#define A_PAIR_B  (TILE_E * A_ROW_B)    // 8704 per pair
#define SM_A      0
#define SM_B      (N_PAIRS * A_PAIR_B)  // 139264: 8 ks x 4 ns-pairs x 32 lanes x uint4
#define SM_PAR    (SM_B + 8 * 4 * 32 * 16)   // +16384 -> 155648
#define SM_PB     (SM_PAR + 136 * 4)    // pair partial buffers: 16 x 64 floats
#define SM_BYTES  (SM_PB + N_PAIRS * 64 * 4) // 160288 < 232448

__device__ uint2 g_xh[MAX_NODES * 32];  // x in fp16: 32 x uint2 (=128 fp16) per row

__device__ __forceinline__ uint32_t smem_u32(const void* p) {
    uint32_t a;
    asm("{ .reg .u64 t; cvta.to.shared.u64 t, %1; cvt.u32.u64 %0, t; }" : "=r"(a) : "l"(p));
    return a;
}
__device__ __forceinline__ uint32_t lds32(uint32_t addr) {
    uint32_t v;
    asm volatile("ld.shared.b32 %0, [%1];" : "=r"(v) : "r"(addr));
    return v;
}
__device__ __forceinline__ uint4 lds128(uint32_t addr) {
    uint4 v;
    asm volatile("ld.shared.v4.b32 {%0,%1,%2,%3}, [%4];"
                 : "=r"(v.x), "=r"(v.y), "=r"(v.z), "=r"(v.w) : "r"(addr));
    return v;
}
__device__ __forceinline__ void sts64(uint32_t addr, uint2 v) {
    asm volatile("st.shared.v2.b32 [%0], {%1,%2};" :: "r"(addr), "r"(v.x), "r"(v.y));
}
#define PAIR_BAR(id) asm volatile("bar.sync %0, 64;" :: "r"(id) : "memory")

// pack two f32 into f16x2 word: lo arg -> lower half, hi arg -> upper half.
__device__ __forceinline__ uint32_t pack_f16x2(float lo, float hi) {
    uint32_t u;
    asm("cvt.rn.f16x2.f32 %0, %1, %2;" : "=r"(u) : "f"(hi), "f"(lo));
    return u;
}
// |a - b| on packed fp16x2
__device__ __forceinline__ uint32_t habs_diff2(uint32_t a, uint32_t b) {
    __half2 d = __habs2(__hsub2(*(__half2*)&a, *(__half2*)&b));
    return *(uint32_t*)&d;
}

__device__ __forceinline__ void mma_f16(float* c, const uint32_t* a,
                                        uint32_t b0, uint32_t b1) {
    asm volatile(
        "mma.sync.aligned.m16n8k16.row.col.f32.f16.f16.f32 "
        "{%0,%1,%2,%3}, {%4,%5,%6,%7}, {%8,%9}, {%0,%1,%2,%3};"
        : "+f"(c[0]), "+f"(c[1]), "+f"(c[2]), "+f"(c[3])
        : "r"(a[0]), "r"(a[1]), "r"(a[2]), "r"(a[3]), "r"(b0), "r"(b1));
}

// Load one m16k16 A fragment (4 u32): rows g, g+8; col words 2t.., 2t+8..
__device__ __forceinline__ void ld_afrag(uint32_t* f, uint32_t base, int g, uint32_t cb) {
    uint32_t r0 = base + (uint32_t)g * A_ROW_B + cb;
    uint32_t r8 = r0 + 8 * A_ROW_B;
    f[0] = lds32(r0);
    f[1] = lds32(r8);
    f[2] = lds32(r0 + 16);
    f[3] = lds32(r8 + 16);
}

// ---- prepass: convert x (f32) -> fp16 rows in g_xh ----
__global__ void convert_x_kernel(const float4* __restrict__ x4, int n_quads) {
    int i = blockIdx.x * blockDim.x + threadIdx.x;   // one float4 -> one uint2
    if (i < n_quads) {
        float4 v = x4[i];
        g_xh[i] = make_uint2(pack_f16x2(v.x, v.y), pack_f16x2(v.z, v.w));
    }
}

__global__ void __launch_bounds__(THREADS, 1) edge_mlp(
    const int* __restrict__ idx32,
    const float* __restrict__ W1, const float* __restrict__ b1,
    const float* __restrict__ W2, const float* __restrict__ b2,
    float* __restrict__ out, int n_edges, int n_nodes,
    int n_tiles, int n_pairs_total)
{
    extern __shared__ char smem[];
    const uint32_t sb = smem_u32(smem);
    const int tid = threadIdx.x, wid = tid >> 5, lid = tid & 31;
    float* par = (float*)(smem + SM_PAR);
    int* flag = (int*)(par + 132);
    float* pb  = (float*)(smem + SM_PB);

    // ---- inline index-dtype detection (warp 0): int64 nonneg => all high
    // words zero; int32 => "high words" are random indices, OR != 0 w.h.p. ----
    if (wid == 0) {
        int j = lid < n_edges ? lid : 0;
        int v = idx32[2 * j + 1];
        v = __reduce_or_sync(0xffffffffu, v);
        if (lid == 0) *flag = (v == 0) ? 1 : 0;
    }

    // ---- one-time: stage W1 as per-lane fp16 B fragments, 2 ns per uint4 ----
    for (int e = tid; e < 2048; e += THREADS) {
        int tile = e >> 5, lane = e & 31;
        int ks = tile >> 3, ns = tile & 7;
        int g = lane >> 2, t = lane & 3;
        int col = ns * 8 + g;
        int kb = ks * 16 + 2 * t;
        uint32_t f0 = pack_f16x2(W1[(kb    ) * HID + col], W1[(kb + 1) * HID + col]);
        uint32_t f1 = pack_f16x2(W1[(kb + 8) * HID + col], W1[(kb + 9) * HID + col]);
        uint32_t addr = sb + SM_B + (uint32_t)(((ks * 4 + (ns >> 1)) * 32 + lane) * 16
                                               + (ns & 1) * 8);
        sts64(addr, make_uint2(f0, f1));
    }
    if (tid < HID)            par[tid] = b1[tid];
    else if (tid < 2 * HID)   par[tid] = W2[tid - HID];
    if (tid == 2 * HID)       par[128] = b2[0];
    __syncthreads();

    const int is64 = *flag;
    const int pair = wid >> 1, pid = wid & 1;
    const uint32_t aw = sb + SM_A + (uint32_t)pair * A_PAIR_B;
    const int g2 = lid >> 2, t4 = lid & 3;
    float* mypb = pb + pair * 64;
    int e0_prev = -1;

    // ---- persistent pair-cooperative tile loop (deferred combine) ----
    for (int tile = blockIdx.x * N_PAIRS + pair; tile < n_tiles; tile += n_pairs_total) {
        const int e0 = tile * TILE_E;
        // this warp owns edges [e0 + pid*16, e0 + pid*16 + 16)
        int n0v = 0, n1v = 0;
        {
            int eg = e0 + pid * 16 + (lid & 15);
            if (eg < n_edges) {
                if (is64) {
                    n0v = idx32[2 * eg];
                    n1v = idx32[2 * (n_edges + eg)];
                } else {
                    n0v = idx32[eg];
                    n1v = idx32[n_edges + eg];
                }
            }
            if ((unsigned)n0v >= (unsigned)n_nodes) n0v = 0;
            if ((unsigned)n1v >= (unsigned)n_nodes) n1v = 0;
        }
        __syncwarp();

        // batch-1: issue gather loads for edges 0..7 BEFORE the barrier, so
        // the L2 latency overlaps the rendezvous wait. (acc regs dead here.)
        uint2 va[8], vb[8];
        #pragma unroll
        for (int t = 0; t < 8; t++) {
            int r0 = __shfl_sync(0xffffffffu, n0v, t);
            int r1 = __shfl_sync(0xffffffffu, n1v, t);
            va[t] = __ldg(&g_xh[r0 * 32 + lid]);
            vb[t] = __ldg(&g_xh[r1 * 32 + lid]);
        }

        PAIR_BAR(pair);   // A-buf free (partner's mma of prev tile done);
                          // also orders partner's pb(prev) before our combine

        // deferred combine for previous tile
        if (e0_prev >= 0 && lid < 16) {
            float z = mypb[pid * 16 + lid] + mypb[32 + pid * 16 + lid] + par[128];
            int e = e0_prev + pid * 16 + lid;
            if (e < n_edges) out[e] = 1.f / (1.f + __expf(-z));
        }

        // store batch-1 diffs
        #pragma unroll
        for (int t = 0; t < 8; t++) {
            uint2 d = make_uint2(habs_diff2(va[t].x, vb[t].x),
                                 habs_diff2(va[t].y, vb[t].y));
            sts64(aw + (uint32_t)(pid * 16 + t) * A_ROW_B + (uint32_t)lid * 8, d);
        }
        // batch-2: load + store edges 8..15
        #pragma unroll 4
        for (int t = 8; t < 16; t++) {
            int r0 = __shfl_sync(0xffffffffu, n0v, t);
            int r1 = __shfl_sync(0xffffffffu, n1v, t);
            uint2 a = __ldg(&g_xh[r0 * 32 + lid]);
            uint2 b = __ldg(&g_xh[r1 * 32 + lid]);
            uint2 d = make_uint2(habs_diff2(a.x, b.x), habs_diff2(a.y, b.y));
            sts64(aw + (uint32_t)(pid * 16 + t) * A_ROW_B + (uint32_t)lid * 8, d);
        }

        PAIR_BAR(pair);   // A tile ready

        // ---- MMA: 2 m16-tiles x my 4 ns-tiles x 8 k16-steps ----
        float acc[2][4][4];
        #pragma unroll
        for (int mt = 0; mt < 2; mt++)
            #pragma unroll
            for (int ns = 0; ns < 4; ns++)
                #pragma unroll
                for (int c = 0; c < 4; c++) acc[mt][ns][c] = 0.f;

        #pragma unroll 2
        for (int ks = 0; ks < 8; ks++) {
            uint32_t a0[4], a1[4];
            const uint32_t cb = (uint32_t)(ks * 32 + t4 * 4);
            ld_afrag(a0, aw, g2, cb);
            ld_afrag(a1, aw + 16 * A_ROW_B, g2, cb);
            const uint32_t bbase = sb + SM_B
                + (uint32_t)(ks * 2048 + (2 * pid) * 512 + lid * 16);
            #pragma unroll
            for (int i = 0; i < 2; i++) {
                uint4 B = lds128(bbase + i * 512);
                mma_f16(acc[0][2 * i],     a0, B.x, B.y);
                mma_f16(acc[1][2 * i],     a1, B.x, B.y);
                mma_f16(acc[0][2 * i + 1], a0, B.z, B.w);
                mma_f16(acc[1][2 * i + 1], a1, B.z, B.w);
            }
        }

        // ---- epilogue: partial z over my 32 hidden cols -> pb ----
        #pragma unroll
        for (int mt = 0; mt < 2; mt++) {
            float za = 0.f, zb = 0.f;
            #pragma unroll
            for (int i = 0; i < 4; i++) {
                int nsg = 4 * pid + i;
                int c0 = nsg * 8 + 2 * t4, c1 = c0 + 1;
                float h;
                h = fmaxf(acc[mt][i][0] + par[c0], 0.f); za = fmaf(h, par[64 + c0], za);
                h = fmaxf(acc[mt][i][1] + par[c1], 0.f); za = fmaf(h, par[64 + c1], za);
                h = fmaxf(acc[mt][i][2] + par[c0], 0.f); zb = fmaf(h, par[64 + c0], zb);
                h = fmaxf(acc[mt][i][3] + par[c1], 0.f); zb = fmaf(h, par[64 + c1], zb);
            }
            za += __shfl_xor_sync(0xffffffffu, za, 1);
            za += __shfl_xor_sync(0xffffffffu, za, 2);
            zb += __shfl_xor_sync(0xffffffffu, zb, 1);
            zb += __shfl_xor_sync(0xffffffffu, zb, 2);
            if (t4 == 0) {
                mypb[pid * 32 + mt * 16 + g2]     = za;
                mypb[pid * 32 + mt * 16 + 8 + g2] = zb;
            }
        }
        e0_prev = e0;
    }

    // ---- drain: final combine for the last tile ----
    if (e0_prev >= 0) {
        PAIR_BAR(pair);
        if (lid < 16) {
            float z = mypb[pid * 16 + lid] + mypb[32 + pid * 16 + lid] + par[128];
            int e = e0_prev + pid * 16 + lid;
            if (e < n_edges) out[e] = 1.f / (1.f + __expf(-z));
        }
    }
}

extern "C" void kernel_launch(void* const* d_in, const int* in_sizes, int n_in,
                              void* d_out, int out_size) {
    const float* x   = (const float*)d_in[0];
    const int*   idx = (const int*)d_in[1];
    const float* W1  = (const float*)d_in[2];
    const float* b1  = (const float*)d_in[3];
    const float* W2  = (const float*)d_in[4];
    const float* b2  = (const float*)d_in[5];
    float*       out = (float*)d_out;

    int n_edges = in_sizes[1] / 2;                 // indices is [2, n_edges]
    int n_nodes = in_sizes[0] / D_FEAT;            // x is [n_nodes, 128] f32
    if (n_nodes > MAX_NODES) n_nodes = MAX_NODES;
    int n_tiles = (n_edges + TILE_E - 1) / TILE_E;

    int sms = 148;
    cudaDeviceGetAttribute(&sms, cudaDevAttrMultiProcessorCount, 0);

    int n_quads = n_nodes * 32;                    // one float4 per uint2 row chunk
    convert_x_kernel<<<(n_quads + 255) / 256, 256>>>((const float4*)x, n_quads);

    cudaFuncSetAttribute(edge_mlp, cudaFuncAttributeMaxDynamicSharedMemorySize, SM_BYTES);
    edge_mlp<<<sms, THREADS, SM_BYTES>>>(idx, W1, b1, W2, b2,
                                         out, n_edges, n_nodes, n_tiles,
                                         sms * N_PAIRS);
}

// round 15
// speedup vs baseline: 1.4887x; 1.0711x over previous
#include <cuda_runtime.h>
#include <cuda_fp16.h>
#include <cstdint>

// ============================================================================
// EdgeCompute: out[e] = sigmoid(relu(|x[i0[e]] - x[i1[e]]| @ W1 + b1) @ W2 + b2)
// R14: instruction-count compression on the R13 warp-pair kernel (traffic,
// registers, and math unchanged):
//  - A fragments via ldmatrix.m8n8.x4 (2 inst/ks vs 8 lds32 + addr math)
//  - gather via paired-row ldg.128 (lanes 0-15 edge t, 16-31 edge t+1)
//  - A-tile stores via sts128 (1 inst per 2 rows)
// Pair protocol unchanged: [idx+ldg8 | barA | combine(t-1) | sts | ldg+sts |
// barB | mma | pb-write]; drain bar + combine after the loop.
// 32 warps/CTA, pure fp16 single-term m16n8k16, x pre-converted to fp16.
// ============================================================================

#define D_FEAT 128
#define HID 64
#define WPC 32
#define THREADS (WPC * 32)
#define N_PAIRS (WPC / 2)
#define TILE_E 32
#define MAX_NODES 16384

#define A_ROW_B   272                   // 128 fp16 + 16B pad -> conflict-free frags
#define A_PAIR_B  (TILE_E * A_ROW_B)    // 8704 per pair
#define SM_A      0
#define SM_B      (N_PAIRS * A_PAIR_B)  // 139264: 8 ks x 4 ns-pairs x 32 lanes x uint4
#define SM_PAR    (SM_B + 8 * 4 * 32 * 16)   // +16384 -> 155648
#define SM_PB     (SM_PAR + 136 * 4)    // pair partial buffers: 16 x 64 floats
#define SM_BYTES  (SM_PB + N_PAIRS * 64 * 4) // 160288 < 232448

__device__ uint4 g_xh[MAX_NODES * 16];  // x in fp16: 16 x uint4 (=128 fp16) per row

__device__ __forceinline__ uint32_t smem_u32(const void* p) {
    uint32_t a;
    asm("{ .reg .u64 t; cvta.to.shared.u64 t, %1; cvt.u32.u64 %0, t; }" : "=r"(a) : "l"(p));
    return a;
}
__device__ __forceinline__ uint4 lds128(uint32_t addr) {
    uint4 v;
    asm volatile("ld.shared.v4.b32 {%0,%1,%2,%3}, [%4];"
                 : "=r"(v.x), "=r"(v.y), "=r"(v.z), "=r"(v.w) : "r"(addr));
    return v;
}
__device__ __forceinline__ void sts64(uint32_t addr, uint2 v) {
    asm volatile("st.shared.v2.b32 [%0], {%1,%2};" :: "r"(addr), "r"(v.x), "r"(v.y));
}
__device__ __forceinline__ void sts128(uint32_t addr, uint4 v) {
    asm volatile("st.shared.v4.b32 [%0], {%1,%2,%3,%4};"
                 :: "r"(addr), "r"(v.x), "r"(v.y), "r"(v.z), "r"(v.w));
}
// ldmatrix x4: lane addressing (lid%16 -> row, lid/16 -> 16B col-half) yields
// frag order {rows g, rows g+8, cols+8 rows g, cols+8 rows g+8} = mma A order.
__device__ __forceinline__ void ldmat4(uint32_t* d, uint32_t addr) {
    asm volatile("ldmatrix.sync.aligned.m8n8.x4.shared.b16 {%0,%1,%2,%3}, [%4];"
                 : "=r"(d[0]), "=r"(d[1]), "=r"(d[2]), "=r"(d[3]) : "r"(addr));
}
#define PAIR_BAR(id) asm volatile("bar.sync %0, 64;" :: "r"(id) : "memory")

// pack two f32 into f16x2 word: lo arg -> lower half, hi arg -> upper half.
__device__ __forceinline__ uint32_t pack_f16x2(float lo, float hi) {
    uint32_t u;
    asm("cvt.rn.f16x2.f32 %0, %1, %2;" : "=r"(u) : "f"(hi), "f"(lo));
    return u;
}
// |a - b| on packed fp16x2
__device__ __forceinline__ uint32_t habs_diff2(uint32_t a, uint32_t b) {
    __half2 d = __habs2(__hsub2(*(__half2*)&a, *(__half2*)&b));
    return *(uint32_t*)&d;
}
__device__ __forceinline__ uint4 diff4(uint4 a, uint4 b) {
    return make_uint4(habs_diff2(a.x, b.x), habs_diff2(a.y, b.y),
                      habs_diff2(a.z, b.z), habs_diff2(a.w, b.w));
}

__device__ __forceinline__ void mma_f16(float* c, const uint32_t* a,
                                        uint32_t b0, uint32_t b1) {
    asm volatile(
        "mma.sync.aligned.m16n8k16.row.col.f32.f16.f16.f32 "
        "{%0,%1,%2,%3}, {%4,%5,%6,%7}, {%8,%9}, {%0,%1,%2,%3};"
        : "+f"(c[0]), "+f"(c[1]), "+f"(c[2]), "+f"(c[3])
        : "r"(a[0]), "r"(a[1]), "r"(a[2]), "r"(a[3]), "r"(b0), "r"(b1));
}

// ---- prepass: convert x (f32) -> fp16 rows in g_xh (uint4 = 8 features) ----
__global__ void convert_x_kernel(const float4* __restrict__ x4, int n_oct) {
    int i = blockIdx.x * blockDim.x + threadIdx.x;   // one uint4 out = 2 float4 in
    if (i < n_oct) {
        float4 v0 = x4[2 * i], v1 = x4[2 * i + 1];
        g_xh[i] = make_uint4(pack_f16x2(v0.x, v0.y), pack_f16x2(v0.z, v0.w),
                             pack_f16x2(v1.x, v1.y), pack_f16x2(v1.z, v1.w));
    }
}

__global__ void __launch_bounds__(THREADS, 1) edge_mlp(
    const int* __restrict__ idx32,
    const float* __restrict__ W1, const float* __restrict__ b1,
    const float* __restrict__ W2, const float* __restrict__ b2,
    float* __restrict__ out, int n_edges, int n_nodes,
    int n_tiles, int n_pairs_total)
{
    extern __shared__ char smem[];
    const uint32_t sb = smem_u32(smem);
    const int tid = threadIdx.x, wid = tid >> 5, lid = tid & 31;
    float* par = (float*)(smem + SM_PAR);
    int* flag = (int*)(par + 132);
    float* pb  = (float*)(smem + SM_PB);

    // ---- inline index-dtype detection (warp 0): int64 nonneg => all high
    // words zero; int32 => "high words" are random indices, OR != 0 w.h.p. ----
    if (wid == 0) {
        int j = lid < n_edges ? lid : 0;
        int v = idx32[2 * j + 1];
        v = __reduce_or_sync(0xffffffffu, v);
        if (lid == 0) *flag = (v == 0) ? 1 : 0;
    }

    // ---- one-time: stage W1 as per-lane fp16 B fragments, 2 ns per uint4 ----
    for (int e = tid; e < 2048; e += THREADS) {
        int tile = e >> 5, lane = e & 31;
        int ks = tile >> 3, ns = tile & 7;
        int g = lane >> 2, t = lane & 3;
        int col = ns * 8 + g;
        int kb = ks * 16 + 2 * t;
        uint32_t f0 = pack_f16x2(W1[(kb    ) * HID + col], W1[(kb + 1) * HID + col]);
        uint32_t f1 = pack_f16x2(W1[(kb + 8) * HID + col], W1[(kb + 9) * HID + col]);
        uint32_t addr = sb + SM_B + (uint32_t)(((ks * 4 + (ns >> 1)) * 32 + lane) * 16
                                               + (ns & 1) * 8);
        sts64(addr, make_uint2(f0, f1));
    }
    if (tid < HID)            par[tid] = b1[tid];
    else if (tid < 2 * HID)   par[tid] = W2[tid - HID];
    if (tid == 2 * HID)       par[128] = b2[0];
    __syncthreads();

    const int is64 = *flag;
    const int pair = wid >> 1, pid = wid & 1;
    const uint32_t aw = sb + SM_A + (uint32_t)pair * A_PAIR_B;
    const int g2 = lid >> 2, t4 = lid & 3;
    const int hsel = lid >> 4;            // 0: edge t, 1: edge t+1
    const int l16 = lid & 15;
    // ldmatrix lane address: row = lid%16, col-half = lid/16
    const uint32_t lmbase = aw + (uint32_t)l16 * A_ROW_B + (uint32_t)hsel * 16;
    float* mypb = pb + pair * 64;
    int e0_prev = -1;

    // ---- persistent pair-cooperative tile loop (deferred combine) ----
    for (int tile = blockIdx.x * N_PAIRS + pair; tile < n_tiles; tile += n_pairs_total) {
        const int e0 = tile * TILE_E;
        // this warp owns edges [e0 + pid*16, e0 + pid*16 + 16)
        int n0v = 0, n1v = 0;
        {
            int eg = e0 + pid * 16 + l16;
            if (eg < n_edges) {
                if (is64) {
                    n0v = idx32[2 * eg];
                    n1v = idx32[2 * (n_edges + eg)];
                } else {
                    n0v = idx32[eg];
                    n1v = idx32[n_edges + eg];
                }
            }
            if ((unsigned)n0v >= (unsigned)n_nodes) n0v = 0;
            if ((unsigned)n1v >= (unsigned)n_nodes) n1v = 0;
        }
        __syncwarp();

        // batch-1: gather loads for edges 0..7 BEFORE the barrier (paired
        // rows: lanes 0-15 edge 2i, lanes 16-31 edge 2i+1; 16B per lane).
        uint4 va[4], vb[4];
        #pragma unroll
        for (int i = 0; i < 4; i++) {
            int tt = 2 * i + hsel;
            int r0 = __shfl_sync(0xffffffffu, n0v, tt);
            int r1 = __shfl_sync(0xffffffffu, n1v, tt);
            va[i] = __ldg(&g_xh[r0 * 16 + l16]);
            vb[i] = __ldg(&g_xh[r1 * 16 + l16]);
        }

        PAIR_BAR(pair);   // A-buf free (partner's mma of prev tile done);
                          // also orders partner's pb(prev) before our combine

        // deferred combine for previous tile
        if (e0_prev >= 0 && lid < 16) {
            float z = mypb[pid * 16 + lid] + mypb[32 + pid * 16 + lid] + par[128];
            int e = e0_prev + pid * 16 + lid;
            if (e < n_edges) out[e] = 1.f / (1.f + __expf(-z));
        }

        // store batch-1 diffs (one sts128 covers 2 rows across the warp)
        #pragma unroll
        for (int i = 0; i < 4; i++) {
            uint32_t row = (uint32_t)(pid * 16 + 2 * i + hsel);
            sts128(aw + row * A_ROW_B + (uint32_t)l16 * 16, diff4(va[i], vb[i]));
        }
        // batch-2: load + store edges 8..15
        #pragma unroll
        for (int i = 4; i < 8; i++) {
            int tt = 2 * i + hsel;
            int r0 = __shfl_sync(0xffffffffu, n0v, tt);
            int r1 = __shfl_sync(0xffffffffu, n1v, tt);
            uint4 a = __ldg(&g_xh[r0 * 16 + l16]);
            uint4 b = __ldg(&g_xh[r1 * 16 + l16]);
            uint32_t row = (uint32_t)(pid * 16 + 2 * i + hsel);
            sts128(aw + row * A_ROW_B + (uint32_t)l16 * 16, diff4(a, b));
        }

        PAIR_BAR(pair);   // A tile ready

        // ---- MMA: 2 m16-tiles x my 4 ns-tiles x 8 k16-steps ----
        float acc[2][4][4];
        #pragma unroll
        for (int mt = 0; mt < 2; mt++)
            #pragma unroll
            for (int ns = 0; ns < 4; ns++)
                #pragma unroll
                for (int c = 0; c < 4; c++) acc[mt][ns][c] = 0.f;

        #pragma unroll 2
        for (int ks = 0; ks < 8; ks++) {
            uint32_t a0[4], a1[4];
            ldmat4(a0, lmbase + (uint32_t)(ks * 32));
            ldmat4(a1, lmbase + (uint32_t)(16 * A_ROW_B + ks * 32));
            const uint32_t bbase = sb + SM_B
                + (uint32_t)(ks * 2048 + (2 * pid) * 512 + lid * 16);
            #pragma unroll
            for (int i = 0; i < 2; i++) {
                uint4 B = lds128(bbase + i * 512);
                mma_f16(acc[0][2 * i],     a0, B.x, B.y);
                mma_f16(acc[1][2 * i],     a1, B.x, B.y);
                mma_f16(acc[0][2 * i + 1], a0, B.z, B.w);
                mma_f16(acc[1][2 * i + 1], a1, B.z, B.w);
            }
        }

        // ---- epilogue: partial z over my 32 hidden cols -> pb ----
        #pragma unroll
        for (int mt = 0; mt < 2; mt++) {
            float za = 0.f, zb = 0.f;
            #pragma unroll
            for (int i = 0; i < 4; i++) {
                int nsg = 4 * pid + i;
                int c0 = nsg * 8 + 2 * t4, c1 = c0 + 1;
                float h;
                h = fmaxf(acc[mt][i][0] + par[c0], 0.f); za = fmaf(h, par[64 + c0], za);
                h = fmaxf(acc[mt][i][1] + par[c1], 0.f); za = fmaf(h, par[64 + c1], za);
                h = fmaxf(acc[mt][i][2] + par[c0], 0.f); zb = fmaf(h, par[64 + c0], zb);
                h = fmaxf(acc[mt][i][3] + par[c1], 0.f); zb = fmaf(h, par[64 + c1], zb);
            }
            za += __shfl_xor_sync(0xffffffffu, za, 1);
            za += __shfl_xor_sync(0xffffffffu, za, 2);
            zb += __shfl_xor_sync(0xffffffffu, zb, 1);
            zb += __shfl_xor_sync(0xffffffffu, zb, 2);
            if (t4 == 0) {
                mypb[pid * 32 + mt * 16 + g2]     = za;
                mypb[pid * 32 + mt * 16 + 8 + g2] = zb;
            }
        }
        e0_prev = e0;
    }

    // ---- drain: final combine for the last tile ----
    if (e0_prev >= 0) {
        PAIR_BAR(pair);
        if (lid < 16) {
            float z = mypb[pid * 16 + lid] + mypb[32 + pid * 16 + lid] + par[128];
            int e = e0_prev + pid * 16 + lid;
            if (e < n_edges) out[e] = 1.f / (1.f + __expf(-z));
        }
    }
}

extern "C" void kernel_launch(void* const* d_in, const int* in_sizes, int n_in,
                              void* d_out, int out_size) {
    const float* x   = (const float*)d_in[0];
    const int*   idx = (const int*)d_in[1];
    const float* W1  = (const float*)d_in[2];
    const float* b1  = (const float*)d_in[3];
    const float* W2  = (const float*)d_in[4];
    const float* b2  = (const float*)d_in[5];
    float*       out = (float*)d_out;

    int n_edges = in_sizes[1] / 2;                 // indices is [2, n_edges]
    int n_nodes = in_sizes[0] / D_FEAT;            // x is [n_nodes, 128] f32
    if (n_nodes > MAX_NODES) n_nodes = MAX_NODES;
    int n_tiles = (n_edges + TILE_E - 1) / TILE_E;

    int sms = 148;
    cudaDeviceGetAttribute(&sms, cudaDevAttrMultiProcessorCount, 0);

    int n_oct = n_nodes * 16;                      // one uint4 per 8 features
    convert_x_kernel<<<(n_oct + 255) / 256, 256>>>((const float4*)x, n_oct);

    cudaFuncSetAttribute(edge_mlp, cudaFuncAttributeMaxDynamicSharedMemorySize, SM_BYTES);
    edge_mlp<<<sms, THREADS, SM_BYTES>>>(idx, W1, b1, W2, b2,
                                         out, n_edges, n_nodes, n_tiles,
                                         sms * N_PAIRS);
}

// round 16
// speedup vs baseline: 1.5166x; 1.0187x over previous
#include <cuda_runtime.h>
#include <cuda_fp16.h>
#include <cstdint>

// ============================================================================
// EdgeCompute: out[e] = sigmoid(relu(|x[i0[e]] - x[i1[e]]| @ W1 + b1) @ W2 + b2)
// R15: dynamic tile scheduling. With TILE_E=32 there are only ~8.2 tiles per
// warp-pair; static striding quantizes (22% of pairs run 9 tiles -> ~9% tail
// waste, plus per-SM speed variance). Pairs now pull tiles from a global
// atomic counter: pid-0 fetches the NEXT tile mid-tile (latency hidden under
// batch-2 gather), publishes via a pair slot ordered by the existing
// barriers. Counter reset by the convert prepass each launch (graph-safe).
// Everything else unchanged from R14: warp-pair 32-edge tiles, ns-split 4/4,
// ldmatrix A-frags, paired-row ldg.128 gather, sts128 stores, deferred
// combine, 32 warps/CTA, pure fp16 single-term m16n8k16, x pre-conv to fp16.
// ============================================================================

#define D_FEAT 128
#define HID 64
#define WPC 32
#define THREADS (WPC * 32)
#define N_PAIRS (WPC / 2)
#define TILE_E 32
#define MAX_NODES 16384

#define A_ROW_B   272                   // 128 fp16 + 16B pad -> conflict-free frags
#define A_PAIR_B  (TILE_E * A_ROW_B)    // 8704 per pair
#define SM_A      0
#define SM_B      (N_PAIRS * A_PAIR_B)  // 139264: 8 ks x 4 ns-pairs x 32 lanes x uint4
#define SM_PAR    (SM_B + 8 * 4 * 32 * 16)   // +16384 -> 155648
#define SM_PB     (SM_PAR + 136 * 4)    // pair partial buffers: 16 x 64 floats
#define SM_TS     (SM_PB + N_PAIRS * 64 * 4) // per-pair next-tile slots (16 ints)
#define SM_BYTES  (SM_TS + N_PAIRS * 4) // 160352 < 232448

__device__ uint4 g_xh[MAX_NODES * 16];  // x in fp16: 16 x uint4 (=128 fp16) per row
__device__ unsigned int g_tile_ctr;     // dynamic tile counter (reset by prepass)

__device__ __forceinline__ uint32_t smem_u32(const void* p) {
    uint32_t a;
    asm("{ .reg .u64 t; cvta.to.shared.u64 t, %1; cvt.u32.u64 %0, t; }" : "=r"(a) : "l"(p));
    return a;
}
__device__ __forceinline__ uint4 lds128(uint32_t addr) {
    uint4 v;
    asm volatile("ld.shared.v4.b32 {%0,%1,%2,%3}, [%4];"
                 : "=r"(v.x), "=r"(v.y), "=r"(v.z), "=r"(v.w) : "r"(addr));
    return v;
}
__device__ __forceinline__ void sts64(uint32_t addr, uint2 v) {
    asm volatile("st.shared.v2.b32 [%0], {%1,%2};" :: "r"(addr), "r"(v.x), "r"(v.y));
}
__device__ __forceinline__ void sts128(uint32_t addr, uint4 v) {
    asm volatile("st.shared.v4.b32 [%0], {%1,%2,%3,%4};"
                 :: "r"(addr), "r"(v.x), "r"(v.y), "r"(v.z), "r"(v.w));
}
// ldmatrix x4: lane addressing (lid%16 -> row, lid/16 -> 16B col-half) yields
// frag order {rows g, rows g+8, cols+8 rows g, cols+8 rows g+8} = mma A order.
__device__ __forceinline__ void ldmat4(uint32_t* d, uint32_t addr) {
    asm volatile("ldmatrix.sync.aligned.m8n8.x4.shared.b16 {%0,%1,%2,%3}, [%4];"
                 : "=r"(d[0]), "=r"(d[1]), "=r"(d[2]), "=r"(d[3]) : "r"(addr));
}
#define PAIR_BAR(id) asm volatile("bar.sync %0, 64;" :: "r"(id) : "memory")

// pack two f32 into f16x2 word: lo arg -> lower half, hi arg -> upper half.
__device__ __forceinline__ uint32_t pack_f16x2(float lo, float hi) {
    uint32_t u;
    asm("cvt.rn.f16x2.f32 %0, %1, %2;" : "=r"(u) : "f"(hi), "f"(lo));
    return u;
}
// |a - b| on packed fp16x2
__device__ __forceinline__ uint32_t habs_diff2(uint32_t a, uint32_t b) {
    __half2 d = __habs2(__hsub2(*(__half2*)&a, *(__half2*)&b));
    return *(uint32_t*)&d;
}
__device__ __forceinline__ uint4 diff4(uint4 a, uint4 b) {
    return make_uint4(habs_diff2(a.x, b.x), habs_diff2(a.y, b.y),
                      habs_diff2(a.z, b.z), habs_diff2(a.w, b.w));
}

__device__ __forceinline__ void mma_f16(float* c, const uint32_t* a,
                                        uint32_t b0, uint32_t b1) {
    asm volatile(
        "mma.sync.aligned.m16n8k16.row.col.f32.f16.f16.f32 "
        "{%0,%1,%2,%3}, {%4,%5,%6,%7}, {%8,%9}, {%0,%1,%2,%3};"
        : "+f"(c[0]), "+f"(c[1]), "+f"(c[2]), "+f"(c[3])
        : "r"(a[0]), "r"(a[1]), "r"(a[2]), "r"(a[3]), "r"(b0), "r"(b1));
}

// ---- prepass: convert x (f32) -> fp16 rows in g_xh; reset tile counter ----
__global__ void convert_x_kernel(const float4* __restrict__ x4, int n_oct) {
    int i = blockIdx.x * blockDim.x + threadIdx.x;   // one uint4 out = 2 float4 in
    if (i == 0) g_tile_ctr = 0;
    if (i < n_oct) {
        float4 v0 = x4[2 * i], v1 = x4[2 * i + 1];
        g_xh[i] = make_uint4(pack_f16x2(v0.x, v0.y), pack_f16x2(v0.z, v0.w),
                             pack_f16x2(v1.x, v1.y), pack_f16x2(v1.z, v1.w));
    }
}

__global__ void __launch_bounds__(THREADS, 1) edge_mlp(
    const int* __restrict__ idx32,
    const float* __restrict__ W1, const float* __restrict__ b1,
    const float* __restrict__ W2, const float* __restrict__ b2,
    float* __restrict__ out, int n_edges, int n_nodes, int n_tiles)
{
    extern __shared__ char smem[];
    const uint32_t sb = smem_u32(smem);
    const int tid = threadIdx.x, wid = tid >> 5, lid = tid & 31;
    float* par = (float*)(smem + SM_PAR);
    int* flag = (int*)(par + 132);
    float* pb  = (float*)(smem + SM_PB);
    int* ts    = (int*)(smem + SM_TS);

    // ---- inline index-dtype detection (warp 0): int64 nonneg => all high
    // words zero; int32 => "high words" are random indices, OR != 0 w.h.p. ----
    if (wid == 0) {
        int j = lid < n_edges ? lid : 0;
        int v = idx32[2 * j + 1];
        v = __reduce_or_sync(0xffffffffu, v);
        if (lid == 0) *flag = (v == 0) ? 1 : 0;
    }

    // ---- first tile fetch per pair (pid 0, lane 0) ----
    if ((wid & 1) == 0 && lid == 0)
        ts[wid >> 1] = (int)atomicAdd(&g_tile_ctr, 1u);

    // ---- one-time: stage W1 as per-lane fp16 B fragments, 2 ns per uint4 ----
    for (int e = tid; e < 2048; e += THREADS) {
        int tile = e >> 5, lane = e & 31;
        int ks = tile >> 3, ns = tile & 7;
        int g = lane >> 2, t = lane & 3;
        int col = ns * 8 + g;
        int kb = ks * 16 + 2 * t;
        uint32_t f0 = pack_f16x2(W1[(kb    ) * HID + col], W1[(kb + 1) * HID + col]);
        uint32_t f1 = pack_f16x2(W1[(kb + 8) * HID + col], W1[(kb + 9) * HID + col]);
        uint32_t addr = sb + SM_B + (uint32_t)(((ks * 4 + (ns >> 1)) * 32 + lane) * 16
                                               + (ns & 1) * 8);
        sts64(addr, make_uint2(f0, f1));
    }
    if (tid < HID)            par[tid] = b1[tid];
    else if (tid < 2 * HID)   par[tid] = W2[tid - HID];
    if (tid == 2 * HID)       par[128] = b2[0];
    __syncthreads();

    const int is64 = *flag;
    const int pair = wid >> 1, pid = wid & 1;
    const uint32_t aw = sb + SM_A + (uint32_t)pair * A_PAIR_B;
    const int g2 = lid >> 2, t4 = lid & 3;
    const int hsel = lid >> 4;            // 0: edge t, 1: edge t+1
    const int l16 = lid & 15;
    const uint32_t lmbase = aw + (uint32_t)l16 * A_ROW_B + (uint32_t)hsel * 16;
    float* mypb = pb + pair * 64;
    int e0_prev = -1;

    // ---- persistent pair-cooperative dynamic tile loop (deferred combine) ----
    int mytile = ts[pair];                // ordered by __syncthreads
    while (mytile < n_tiles) {
        const int e0 = mytile * TILE_E;
        // this warp owns edges [e0 + pid*16, e0 + pid*16 + 16)
        int n0v = 0, n1v = 0;
        {
            int eg = e0 + pid * 16 + l16;
            if (eg < n_edges) {
                if (is64) {
                    n0v = idx32[2 * eg];
                    n1v = idx32[2 * (n_edges + eg)];
                } else {
                    n0v = idx32[eg];
                    n1v = idx32[n_edges + eg];
                }
            }
            if ((unsigned)n0v >= (unsigned)n_nodes) n0v = 0;
            if ((unsigned)n1v >= (unsigned)n_nodes) n1v = 0;
        }
        __syncwarp();

        // batch-1: gather loads for edges 0..7 BEFORE the barrier (paired
        // rows: lanes 0-15 edge 2i, lanes 16-31 edge 2i+1; 16B per lane).
        uint4 va[4], vb[4];
        #pragma unroll
        for (int i = 0; i < 4; i++) {
            int tt = 2 * i + hsel;
            int r0 = __shfl_sync(0xffffffffu, n0v, tt);
            int r1 = __shfl_sync(0xffffffffu, n1v, tt);
            va[i] = __ldg(&g_xh[r0 * 16 + l16]);
            vb[i] = __ldg(&g_xh[r1 * 16 + l16]);
        }

        PAIR_BAR(pair);   // A-buf free (partner's mma of prev tile done);
                          // also orders partner's pb(prev) before our combine

        // deferred combine for previous tile
        if (e0_prev >= 0 && lid < 16) {
            float z = mypb[pid * 16 + lid] + mypb[32 + pid * 16 + lid] + par[128];
            int e = e0_prev + pid * 16 + lid;
            if (e < n_edges) out[e] = 1.f / (1.f + __expf(-z));
        }

        // fetch NEXT tile (pid 0): atomic latency hides under batch-2 gather;
        // slot write is ordered before partner's read by barB below.
        if (pid == 0 && lid == 0)
            ts[pair] = (int)atomicAdd(&g_tile_ctr, 1u);

        // store batch-1 diffs (one sts128 covers 2 rows across the warp)
        #pragma unroll
        for (int i = 0; i < 4; i++) {
            uint32_t row = (uint32_t)(pid * 16 + 2 * i + hsel);
            sts128(aw + row * A_ROW_B + (uint32_t)l16 * 16, diff4(va[i], vb[i]));
        }
        // batch-2: load + store edges 8..15
        #pragma unroll
        for (int i = 4; i < 8; i++) {
            int tt = 2 * i + hsel;
            int r0 = __shfl_sync(0xffffffffu, n0v, tt);
            int r1 = __shfl_sync(0xffffffffu, n1v, tt);
            uint4 a = __ldg(&g_xh[r0 * 16 + l16]);
            uint4 b = __ldg(&g_xh[r1 * 16 + l16]);
            uint32_t row = (uint32_t)(pid * 16 + 2 * i + hsel);
            sts128(aw + row * A_ROW_B + (uint32_t)l16 * 16, diff4(a, b));
        }

        PAIR_BAR(pair);   // A tile ready; also publishes ts[pair]

        // ---- MMA: 2 m16-tiles x my 4 ns-tiles x 8 k16-steps ----
        float acc[2][4][4];
        #pragma unroll
        for (int mt = 0; mt < 2; mt++)
            #pragma unroll
            for (int ns = 0; ns < 4; ns++)
                #pragma unroll
                for (int c = 0; c < 4; c++) acc[mt][ns][c] = 0.f;

        #pragma unroll 2
        for (int ks = 0; ks < 8; ks++) {
            uint32_t a0[4], a1[4];
            ldmat4(a0, lmbase + (uint32_t)(ks * 32));
            ldmat4(a1, lmbase + (uint32_t)(16 * A_ROW_B + ks * 32));
            const uint32_t bbase = sb + SM_B
                + (uint32_t)(ks * 2048 + (2 * pid) * 512 + lid * 16);
            #pragma unroll
            for (int i = 0; i < 2; i++) {
                uint4 B = lds128(bbase + i * 512);
                mma_f16(acc[0][2 * i],     a0, B.x, B.y);
                mma_f16(acc[1][2 * i],     a1, B.x, B.y);
                mma_f16(acc[0][2 * i + 1], a0, B.z, B.w);
                mma_f16(acc[1][2 * i + 1], a1, B.z, B.w);
            }
        }

        // ---- epilogue: partial z over my 32 hidden cols -> pb ----
        #pragma unroll
        for (int mt = 0; mt < 2; mt++) {
            float za = 0.f, zb = 0.f;
            #pragma unroll
            for (int i = 0; i < 4; i++) {
                int nsg = 4 * pid + i;
                int c0 = nsg * 8 + 2 * t4, c1 = c0 + 1;
                float h;
                h = fmaxf(acc[mt][i][0] + par[c0], 0.f); za = fmaf(h, par[64 + c0], za);
                h = fmaxf(acc[mt][i][1] + par[c1], 0.f); za = fmaf(h, par[64 + c1], za);
                h = fmaxf(acc[mt][i][2] + par[c0], 0.f); zb = fmaf(h, par[64 + c0], zb);
                h = fmaxf(acc[mt][i][3] + par[c1], 0.f); zb = fmaf(h, par[64 + c1], zb);
            }
            za += __shfl_xor_sync(0xffffffffu, za, 1);
            za += __shfl_xor_sync(0xffffffffu, za, 2);
            zb += __shfl_xor_sync(0xffffffffu, zb, 1);
            zb += __shfl_xor_sync(0xffffffffu, zb, 2);
            if (t4 == 0) {
                mypb[pid * 32 + mt * 16 + g2]     = za;
                mypb[pid * 32 + mt * 16 + 8 + g2] = zb;
            }
        }
        e0_prev = e0;
        mytile = ts[pair];    // ordered after write by barB above
    }

    // ---- drain: final combine for the last tile ----
    if (e0_prev >= 0) {
        PAIR_BAR(pair);
        if (lid < 16) {
            float z = mypb[pid * 16 + lid] + mypb[32 + pid * 16 + lid] + par[128];
            int e = e0_prev + pid * 16 + lid;
            if (e < n_edges) out[e] = 1.f / (1.f + __expf(-z));
        }
    }
}

extern "C" void kernel_launch(void* const* d_in, const int* in_sizes, int n_in,
                              void* d_out, int out_size) {
    const float* x   = (const float*)d_in[0];
    const int*   idx = (const int*)d_in[1];
    const float* W1  = (const float*)d_in[2];
    const float* b1  = (const float*)d_in[3];
    const float* W2  = (const float*)d_in[4];
    const float* b2  = (const float*)d_in[5];
    float*       out = (float*)d_out;

    int n_edges = in_sizes[1] / 2;                 // indices is [2, n_edges]
    int n_nodes = in_sizes[0] / D_FEAT;            // x is [n_nodes, 128] f32
    if (n_nodes > MAX_NODES) n_nodes = MAX_NODES;
    int n_tiles = (n_edges + TILE_E - 1) / TILE_E;

    int sms = 148;
    cudaDeviceGetAttribute(&sms, cudaDevAttrMultiProcessorCount, 0);

    int n_oct = n_nodes * 16;                      // one uint4 per 8 features
    convert_x_kernel<<<(n_oct + 255) / 256, 256>>>((const float4*)x, n_oct);

    cudaFuncSetAttribute(edge_mlp, cudaFuncAttributeMaxDynamicSharedMemorySize, SM_BYTES);
    edge_mlp<<<sms, THREADS, SM_BYTES>>>(idx, W1, b1, W2, b2,
                                         out, n_edges, n_nodes, n_tiles);
}